// round 3
// baseline (speedup 1.0000x reference)
#include <cuda_runtime.h>

// Problem constants
#define B_    256
#define T_    4
#define S_    2
#define SYM_  14
#define FFT_  128
#define NSC_  108
#define L_    (SYM_ * NSC_)      // 1512
#define MROWS (B_ * T_ * S_)     // 2048
#define ROWSTRIDE (SYM_ * FFT_)  // 1792
#define PLANE ((size_t)MROWS * ROWSTRIDE)  // offset of imag plane in output

// Packed gathered input: Y_r, Y_i as [MROWS][L_] row-major (scratch, ~24.8 MB)
__device__ float g_Ar[(size_t)MROWS * L_];
__device__ float g_Ai[(size_t)MROWS * L_];

// ---------------------------------------------------------------------------
// Kernel 1: gather effective subcarriers + flatten (sym, nsc) -> l
// ---------------------------------------------------------------------------
__global__ void gather_kernel(const float* __restrict__ xr,
                              const float* __restrict__ xi,
                              const int* __restrict__ sc) {
    int idx = blockIdx.x * blockDim.x + threadIdx.x;
    const int total = MROWS * L_;
    if (idx >= total) return;
    int row = idx / L_;
    int l   = idx - row * L_;
    int sym = l / NSC_;
    int j   = l - sym * NSC_;
    size_t src = (size_t)row * ROWSTRIDE + sym * FFT_ + sc[j];
    g_Ar[idx] = xr[src];
    g_Ai[idx] = xi[src];
}

// ---------------------------------------------------------------------------
// Kernel 2: complex GEMM  out[row][m] = sum_l Y[row][l] * conj(C[m][l])
//   real: Yr*Cr + Yi*Ci      imag: Yi*Cr - Yr*Ci
// Tiles: BM=128, BN=64, BK=8; 256 threads; each thread 8x4 complex outputs.
// Epilogue scatters directly into [2, MROWS, SYM, FFT] grid.
// ---------------------------------------------------------------------------
#define BM 128
#define BN 64
#define BK 8
#define TM 8
#define TN 4

__global__ void __launch_bounds__(256, 2)
gemm_kernel(const float* __restrict__ Cr,
            const float* __restrict__ Ci,
            const int* __restrict__ sc,
            float* __restrict__ out) {
    __shared__ __align__(16) float As_r[BK][BM];
    __shared__ __align__(16) float As_i[BK][BM];
    __shared__ __align__(16) float Bs_r[BK][BN];
    __shared__ __align__(16) float Bs_i[BK][BN];
    __shared__ int s_sc[NSC_];

    const int tid = threadIdx.x;
    const int tx  = tid & 15;   // 0..15 -> N direction
    const int ty  = tid >> 4;   // 0..15 -> M direction

    const int rowBase = blockIdx.y * BM;
    const int nBase   = blockIdx.x * BN;

    if (tid < NSC_) s_sc[tid] = sc[tid];

    // A-tile load mapping: 128 rows x 8 k, one float4 per plane per thread
    const int arow = tid >> 1;           // 0..127
    const int akq  = (tid & 1) * 4;      // 0 or 4

    // B-tile load mapping: 64 rows x 8 k x 2 planes, one float4 per thread
    const int bplane = tid >> 7;         // 0: real, 1: imag
    const int brow   = (tid & 127) >> 1; // 0..63
    const int bkq    = (tid & 1) * 4;    // 0 or 4

    const float* __restrict__ A0r = g_Ar + (size_t)rowBase * L_;
    const float* __restrict__ A0i = g_Ai + (size_t)rowBase * L_;

    float accR[TM][TN];
    float accI[TM][TN];
#pragma unroll
    for (int i = 0; i < TM; i++)
#pragma unroll
        for (int j = 0; j < TN; j++) { accR[i][j] = 0.f; accI[i][j] = 0.f; }

    const int gn = nBase + brow;
    const float* __restrict__ Bp = bplane ? Ci : Cr;

    for (int k0 = 0; k0 < L_; k0 += BK) {
        // --- global loads into registers ---
        float4 va_r = *(const float4*)(A0r + (size_t)arow * L_ + k0 + akq);
        float4 va_i = *(const float4*)(A0i + (size_t)arow * L_ + k0 + akq);
        float4 vb = make_float4(0.f, 0.f, 0.f, 0.f);
        if (gn < L_)
            vb = *(const float4*)(Bp + (size_t)gn * L_ + k0 + bkq);

        __syncthreads();   // previous tile fully consumed

        // --- store to smem (transposed: [k][row]) ---
        As_r[akq + 0][arow] = va_r.x;
        As_r[akq + 1][arow] = va_r.y;
        As_r[akq + 2][arow] = va_r.z;
        As_r[akq + 3][arow] = va_r.w;
        As_i[akq + 0][arow] = va_i.x;
        As_i[akq + 1][arow] = va_i.y;
        As_i[akq + 2][arow] = va_i.z;
        As_i[akq + 3][arow] = va_i.w;
        if (bplane == 0) {
            Bs_r[bkq + 0][brow] = vb.x;
            Bs_r[bkq + 1][brow] = vb.y;
            Bs_r[bkq + 2][brow] = vb.z;
            Bs_r[bkq + 3][brow] = vb.w;
        } else {
            Bs_i[bkq + 0][brow] = vb.x;
            Bs_i[bkq + 1][brow] = vb.y;
            Bs_i[bkq + 2][brow] = vb.z;
            Bs_i[bkq + 3][brow] = vb.w;
        }

        __syncthreads();

        // --- compute ---
#pragma unroll
        for (int k = 0; k < BK; k++) {
            float4 ar0 = *(const float4*)&As_r[k][ty * TM];
            float4 ar1 = *(const float4*)&As_r[k][ty * TM + 4];
            float4 ai0 = *(const float4*)&As_i[k][ty * TM];
            float4 ai1 = *(const float4*)&As_i[k][ty * TM + 4];
            float4 br4 = *(const float4*)&Bs_r[k][tx * TN];
            float4 bi4 = *(const float4*)&Bs_i[k][tx * TN];

            float ar[TM] = {ar0.x, ar0.y, ar0.z, ar0.w, ar1.x, ar1.y, ar1.z, ar1.w};
            float ai[TM] = {ai0.x, ai0.y, ai0.z, ai0.w, ai1.x, ai1.y, ai1.z, ai1.w};
            float br[TN] = {br4.x, br4.y, br4.z, br4.w};
            float bi[TN] = {bi4.x, bi4.y, bi4.z, bi4.w};

#pragma unroll
            for (int i = 0; i < TM; i++) {
#pragma unroll
                for (int j = 0; j < TN; j++) {
                    accR[i][j] += ar[i] * br[j];
                    accR[i][j] += ai[i] * bi[j];
                    accI[i][j] += ai[i] * br[j];
                    accI[i][j] -= ar[i] * bi[j];
                }
            }
        }
    }

    // --- epilogue: scatter into [2, MROWS, SYM, FFT] ---
#pragma unroll
    for (int j = 0; j < TN; j++) {
        int m = nBase + tx * TN + j;
        if (m >= L_) continue;
        int sym = m / NSC_;
        int jj  = m - sym * NSC_;
        int col = sym * FFT_ + s_sc[jj];
#pragma unroll
        for (int i = 0; i < TM; i++) {
            int grow = rowBase + ty * TM + i;
            size_t base = (size_t)grow * ROWSTRIDE + col;
            out[base]         = accR[i][j];
            out[PLANE + base] = accI[i][j];
        }
    }
}

// ---------------------------------------------------------------------------
extern "C" void kernel_launch(void* const* d_in, const int* in_sizes, int n_in,
                              void* d_out, int out_size) {
    const float* xr = (const float*)d_in[0];
    const float* xi = (const float*)d_in[1];
    const float* Cr = (const float*)d_in[2];
    const float* Ci = (const float*)d_in[3];
    const int*   sc = (const int*)d_in[4];
    float* out = (float*)d_out;

    // zero the full output grid (scatter leaves holes that must be 0)
    cudaMemsetAsync(out, 0, sizeof(float) * 2 * PLANE, 0);

    // gather/pack Y
    {
        int total = MROWS * L_;
        int threads = 256;
        int blocks = (total + threads - 1) / threads;
        gather_kernel<<<blocks, threads>>>(xr, xi, sc);
    }

    // complex GEMM + scatter
    {
        dim3 grid((L_ + BN - 1) / BN, MROWS / BM);  // 24 x 16
        gemm_kernel<<<grid, 256>>>(Cr, Ci, sc, out);
    }
}

// round 6
// speedup vs baseline: 1.8516x; 1.8516x over previous
#include <cuda_runtime.h>
#include <cstdint>

// ---------------------------------------------------------------------------
// Problem constants
// ---------------------------------------------------------------------------
#define MROWS 2048            // B*T*S
#define LREAL 1512            // SYM*NSC
#define KPAD  3072            // padded K (2*LREAL -> 3072)
#define NPAD  3072            // padded N
#define NSC_  108
#define SYM_  14
#define FFT_  128
#define ROWSTRIDE 1792        // SYM*FFT
#define PLANE ((size_t)MROWS * ROWSTRIDE)

// GEMM tiling
#define BM 128
#define BN 128
#define BK 32
#define NK (KPAD / BK)        // 96
#define STAGES 4

// padded smem tiles: pitch 36 floats (144 B) kills bank conflicts on frag loads
#define PITCH 36
#define TILE_BYTES (128 * PITCH * 4)             // 18432 per operand per stage
#define STAGE_BYTES (2 * TILE_BYTES)             // A + B
#define SMEM_BYTES (STAGES * STAGE_BYTES)        // 147456

// tf32-rounded operand scratch
__device__ float g_A[(size_t)MROWS * KPAD];   // [row][k]
__device__ float g_B[(size_t)NPAD * KPAD];    // [n][k]

// ---------------------------------------------------------------------------
// PTX helpers (portable: no 'a'-suffix features)
// ---------------------------------------------------------------------------
__device__ __forceinline__ uint32_t smem_u32(const void* p) {
    uint32_t a;
    asm("{ .reg .u64 t; cvta.to.shared.u64 t, %1; cvt.u32.u64 %0, t; }" : "=r"(a) : "l"(p));
    return a;
}
__device__ __forceinline__ uint32_t f2tf32(float x) {
    uint32_t u; asm("cvt.rna.tf32.f32 %0, %1;" : "=r"(u) : "f"(x)); return u;
}
__device__ __forceinline__ void cp_async16(uint32_t saddr, const void* gaddr) {
    asm volatile("cp.async.cg.shared.global [%0], [%1], 16;" :: "r"(saddr), "l"(gaddr));
}
#define CP_COMMIT() asm volatile("cp.async.commit_group;")
#define CP_WAIT(n)  asm volatile("cp.async.wait_group %0;" :: "n"(n))

__device__ __forceinline__ void mma_tf32(float* d, const uint32_t* a, const uint32_t* b) {
    asm volatile(
        "mma.sync.aligned.m16n8k8.row.col.f32.tf32.tf32.f32 "
        "{%0,%1,%2,%3}, {%4,%5,%6,%7}, {%8,%9}, {%0,%1,%2,%3};"
        : "+f"(d[0]), "+f"(d[1]), "+f"(d[2]), "+f"(d[3])
        : "r"(a[0]), "r"(a[1]), "r"(a[2]), "r"(a[3]), "r"(b[0]), "r"(b[1]));
}

// ---------------------------------------------------------------------------
// Prep kernel 1: gather subcarriers, build A = [Yr | Yi] (tf32-rounded)
// ---------------------------------------------------------------------------
__global__ void pack_A(const float* __restrict__ xr, const float* __restrict__ xi,
                       const int* __restrict__ sc) {
    int k   = blockIdx.x * blockDim.x + threadIdx.x;   // 0..3071
    int row = blockIdx.y;                               // 0..2047
    float v = 0.f;
    if (k < 2 * LREAL) {
        int l = (k < LREAL) ? k : k - LREAL;
        int sym = l / NSC_;
        int jj  = l - sym * NSC_;
        size_t src = (size_t)row * ROWSTRIDE + sym * FFT_ + __ldg(&sc[jj]);
        v = (k < LREAL) ? xr[src] : xi[src];
    }
    ((uint32_t*)g_A)[(size_t)row * KPAD + k] = f2tf32(v);
}

// ---------------------------------------------------------------------------
// Prep kernel 2: build B.  rows [0,1512): [Cr | Ci]; rows [1512,3024): [-Ci | Cr]
// ---------------------------------------------------------------------------
__global__ void pack_B(const float* __restrict__ Cr, const float* __restrict__ Ci) {
    int k = blockIdx.x * blockDim.x + threadIdx.x;
    int n = blockIdx.y;
    float v = 0.f;
    if (n < 2 * LREAL && k < 2 * LREAL) {
        int plane = (n >= LREAL);
        int m  = n - plane * LREAL;
        int kp = (k >= LREAL);
        int l  = k - kp * LREAL;
        size_t idx = (size_t)m * LREAL + l;
        if (!plane) v = kp ? Ci[idx] : Cr[idx];
        else        v = kp ? Cr[idx] : -Ci[idx];
    }
    ((uint32_t*)g_B)[(size_t)n * KPAD + k] = f2tf32(v);
}

// ---------------------------------------------------------------------------
// mma.sync tf32 GEMM:  D[2048 x 3072] = A @ B^T, epilogue scatters into grid
// 256 threads = 8 warps (2 x 4). Warp tile 64 x 32. 4-stage cp.async pipeline.
// ---------------------------------------------------------------------------
__global__ void __launch_bounds__(256, 1)
gemm_mma(const int* __restrict__ sc, float* __restrict__ out) {
    extern __shared__ char smem[];
    const uint32_t sb = smem_u32(smem);

    const int tid = threadIdx.x;
    const int wid = tid >> 5;
    const int lid = tid & 31;
    const int wm  = wid >> 2;          // 0..1  (M)
    const int wn  = wid & 3;           // 0..3  (N)
    const int g   = lid >> 2;          // 0..7
    const int tg  = lid & 3;           // 0..3

    const int rowBase = blockIdx.y * BM;
    const int nBase   = blockIdx.x * BN;

    const float* Ag = g_A + (size_t)rowBase * KPAD;
    const float* Bg = g_B + (size_t)nBase * KPAD;

    // cp.async mapping: each thread 4 chunks of 16B per operand per stage
    const int crow = tid >> 1;              // 0..127
    const int cq0  = (tid & 1) * 4;         // 0 or 4

    auto load_stage = [&](int s, int kt) {
        const int k0 = kt * BK;
        const uint32_t abase = sb + s * STAGE_BYTES;
        const uint32_t bbase = abase + TILE_BYTES;
        const float* ag = Ag + (size_t)crow * KPAD + k0;
        const float* bg = Bg + (size_t)crow * KPAD + k0;
#pragma unroll
        for (int i = 0; i < 4; i++) {
            int q = cq0 + i;
            uint32_t o = (uint32_t)(crow * (PITCH * 4) + q * 16);
            cp_async16(abase + o, ag + q * 4);
            cp_async16(bbase + o, bg + q * 4);
        }
    };

    float acc[4][4][4];
#pragma unroll
    for (int mf = 0; mf < 4; mf++)
#pragma unroll
        for (int nf = 0; nf < 4; nf++)
#pragma unroll
            for (int r = 0; r < 4; r++) acc[mf][nf][r] = 0.f;

    // prologue: stages 0..2
#pragma unroll
    for (int s = 0; s < STAGES - 1; s++) {
        load_stage(s, s);
        CP_COMMIT();
    }

    for (int kt = 0; kt < NK; kt++) {
        const int lds = kt + STAGES - 1;
        if (lds < NK) load_stage(lds & (STAGES - 1), lds);
        CP_COMMIT();
        CP_WAIT(STAGES - 1);
        __syncthreads();

        const int s = kt & (STAGES - 1);
        const uint32_t* As = (const uint32_t*)(smem + s * STAGE_BYTES);
        const uint32_t* Bs = (const uint32_t*)(smem + s * STAGE_BYTES + TILE_BYTES);

#pragma unroll
        for (int kk = 0; kk < 4; kk++) {
            const int kb = kk * 8;
            uint32_t af[4][4];
#pragma unroll
            for (int mf = 0; mf < 4; mf++) {
                int row = wm * 64 + mf * 16 + g;
                af[mf][0] = As[row * PITCH + kb + tg];
                af[mf][1] = As[(row + 8) * PITCH + kb + tg];
                af[mf][2] = As[row * PITCH + kb + tg + 4];
                af[mf][3] = As[(row + 8) * PITCH + kb + tg + 4];
            }
            uint32_t bf[4][2];
#pragma unroll
            for (int nf = 0; nf < 4; nf++) {
                int n = wn * 32 + nf * 8 + g;
                bf[nf][0] = Bs[n * PITCH + kb + tg];
                bf[nf][1] = Bs[n * PITCH + kb + tg + 4];
            }
#pragma unroll
            for (int mf = 0; mf < 4; mf++)
#pragma unroll
                for (int nf = 0; nf < 4; nf++)
                    mma_tf32(acc[mf][nf], af[mf], bf[nf]);
        }
        __syncthreads();   // stage s may be overwritten next iteration
    }

    // ---- epilogue: scatter accumulators into [2, MROWS, SYM, FFT] ----
#pragma unroll
    for (int nf = 0; nf < 4; nf++) {
#pragma unroll
        for (int c = 0; c < 2; c++) {
            int n = nBase + wn * 32 + nf * 8 + 2 * tg + c;
            if (n >= 2 * LREAL) continue;
            int plane = (n >= LREAL);
            int m = n - plane * LREAL;
            int sym = m / NSC_;
            int jj  = m - sym * NSC_;
            size_t coladdr = (size_t)plane * PLANE + sym * FFT_ + __ldg(&sc[jj]);
#pragma unroll
            for (int mf = 0; mf < 4; mf++) {
                int row0 = rowBase + wm * 64 + mf * 16 + g;
                out[coladdr + (size_t)row0 * ROWSTRIDE]       = acc[mf][nf][c];
                out[coladdr + (size_t)(row0 + 8) * ROWSTRIDE] = acc[mf][nf][c + 2];
            }
        }
    }
}

// ---------------------------------------------------------------------------
extern "C" void kernel_launch(void* const* d_in, const int* in_sizes, int n_in,
                              void* d_out, int out_size) {
    const float* xr = (const float*)d_in[0];
    const float* xi = (const float*)d_in[1];
    const float* Cr = (const float*)d_in[2];
    const float* Ci = (const float*)d_in[3];
    const int*   sc = (const int*)d_in[4];
    float* out = (float*)d_out;

    cudaFuncSetAttribute(gemm_mma, cudaFuncAttributeMaxDynamicSharedMemorySize, SMEM_BYTES);

    // zero full output grid (scatter leaves guard holes that must be 0)
    cudaMemsetAsync(out, 0, sizeof(float) * 2 * PLANE, 0);

    pack_A<<<dim3(KPAD / 256, MROWS), 256>>>(xr, xi, sc);
    pack_B<<<dim3(KPAD / 256, NPAD), 256>>>(Cr, Ci);

    gemm_mma<<<dim3(NPAD / BN, MROWS / BM), 256, SMEM_BYTES>>>(sc, out);
}

// round 8
// speedup vs baseline: 3.2364x; 1.7479x over previous
#include <cuda_runtime.h>
#include <cstdint>

// ---------------------------------------------------------------------------
// Problem constants
// ---------------------------------------------------------------------------
#define MROWS 2048            // B*T*S
#define LREAL 1512            // SYM*NSC
#define KP    1536            // padded K per panel
#define NP    1536            // padded N per panel
#define NSC_  108
#define SYM_  14
#define FFT_  128
#define ROWSTRIDE 1792        // SYM*FFT
#define PLANE ((size_t)MROWS * ROWSTRIDE)

// GEMM tiling
#define BM 128
#define BN 256
#define BK 32
#define NK (KP / BK)          // 48
#define NTILES (NP / BN)      // 6
#define STAGES 3

// padded smem: pitch 36 floats (144B) -> conflict-free frag LDS
#define PITCH 36
#define A_TILE_BYTES (128 * PITCH * 4)           // 18432
#define B_TILE_BYTES (256 * PITCH * 4)           // 36864
#define STAGE_BYTES (A_TILE_BYTES + B_TILE_BYTES) // 55296
#define SMEM_BYTES (STAGES * STAGE_BYTES)        // 165888

// Karatsuba panels:
//  A0 = Yr+Yi, A1 = Yi, A2 = Yr        (each [2048 x 1536], tf32)
//  B0 = Cr,    B1 = Cr-Ci, B2 = -Cr-Ci (each [1536 x 1536], tf32)
//  D_p = A_p @ B_p^T                   (each [2048 x 1536], fp32)
//  re = D0 - D1,  im = D0 + D2
__device__ float g_A[3][(size_t)MROWS * KP];
__device__ float g_B[3][(size_t)NP * KP];
__device__ float g_D[3][(size_t)MROWS * NP];

// ---------------------------------------------------------------------------
// PTX helpers (portable: no 'a'-suffix features)
// ---------------------------------------------------------------------------
__device__ __forceinline__ uint32_t smem_u32(const void* p) {
    uint32_t a;
    asm("{ .reg .u64 t; cvta.to.shared.u64 t, %1; cvt.u32.u64 %0, t; }" : "=r"(a) : "l"(p));
    return a;
}
__device__ __forceinline__ uint32_t f2tf32(float x) {
    uint32_t u; asm("cvt.rna.tf32.f32 %0, %1;" : "=r"(u) : "f"(x)); return u;
}
__device__ __forceinline__ void cp_async16(uint32_t saddr, const void* gaddr) {
    asm volatile("cp.async.cg.shared.global [%0], [%1], 16;" :: "r"(saddr), "l"(gaddr));
}
#define CP_COMMIT() asm volatile("cp.async.commit_group;")
#define CP_WAIT(n)  asm volatile("cp.async.wait_group %0;" :: "n"(n))

__device__ __forceinline__ void mma_tf32(float* d, const uint32_t* a, const uint32_t* b) {
    asm volatile(
        "mma.sync.aligned.m16n8k8.row.col.f32.tf32.tf32.f32 "
        "{%0,%1,%2,%3}, {%4,%5,%6,%7}, {%8,%9}, {%0,%1,%2,%3};"
        : "+f"(d[0]), "+f"(d[1]), "+f"(d[2]), "+f"(d[3])
        : "r"(a[0]), "r"(a[1]), "r"(a[2]), "r"(a[3]), "r"(b[0]), "r"(b[1]));
}

// ---------------------------------------------------------------------------
// pack_A: gather subcarriers, build 3 A panels (tf32-rounded)
// ---------------------------------------------------------------------------
__global__ void pack_A(const float* __restrict__ xr, const float* __restrict__ xi,
                       const int* __restrict__ sc) {
    int k   = blockIdx.x * blockDim.x + threadIdx.x;   // 0..1535
    int row = blockIdx.y;                               // 0..2047
    float vr = 0.f, vi = 0.f;
    if (k < LREAL) {
        int sym = k / NSC_;
        int jj  = k - sym * NSC_;
        size_t src = (size_t)row * ROWSTRIDE + sym * FFT_ + __ldg(&sc[jj]);
        vr = xr[src];
        vi = xi[src];
    }
    size_t o = (size_t)row * KP + k;
    ((uint32_t*)g_A[0])[o] = f2tf32(vr + vi);
    ((uint32_t*)g_A[1])[o] = f2tf32(vi);
    ((uint32_t*)g_A[2])[o] = f2tf32(vr);
}

// ---------------------------------------------------------------------------
// pack_B: build 3 B panels (tf32-rounded)
// ---------------------------------------------------------------------------
__global__ void pack_B(const float* __restrict__ Cr, const float* __restrict__ Ci) {
    int k = blockIdx.x * blockDim.x + threadIdx.x;     // 0..1535
    int n = blockIdx.y;                                 // 0..1535
    float b0 = 0.f, b1 = 0.f, b2 = 0.f;
    if (n < LREAL && k < LREAL) {
        size_t idx = (size_t)n * LREAL + k;
        float cr = Cr[idx], ci = Ci[idx];
        b0 = cr;
        b1 = cr - ci;
        b2 = -cr - ci;
    }
    size_t o = (size_t)n * KP + k;
    ((uint32_t*)g_B[0])[o] = f2tf32(b0);
    ((uint32_t*)g_B[1])[o] = f2tf32(b1);
    ((uint32_t*)g_B[2])[o] = f2tf32(b2);
}

// ---------------------------------------------------------------------------
// GEMM: D_p[2048 x 1536] = A_p @ B_p^T  (p = blockIdx.x / NTILES)
// 256 threads = 8 warps (2 M x 4 N), warp tile 64 x 64, 3-stage cp.async.
// ---------------------------------------------------------------------------
__global__ void __launch_bounds__(256, 1)
gemm_mma(int dummy) {
    extern __shared__ char smem[];
    const uint32_t sb = smem_u32(smem);

    const int tid = threadIdx.x;
    const int wid = tid >> 5;
    const int lid = tid & 31;
    const int wm  = wid >> 2;          // 0..1  (M)
    const int wn  = wid & 3;           // 0..3  (N)
    const int g   = lid >> 2;          // 0..7
    const int tg  = lid & 3;           // 0..3

    const int p       = blockIdx.x / NTILES;
    const int nBase   = (blockIdx.x - p * NTILES) * BN;
    const int rowBase = blockIdx.y * BM;

    const float* Ag = g_A[p] + (size_t)rowBase * KP;
    const float* Bg = g_B[p] + (size_t)nBase * KP;
    float* Dg = g_D[p];

    // cp.async mapping
    const int crow = tid >> 1;              // 0..127
    const int cq0  = (tid & 1) * 4;         // 0 or 4

    auto load_stage = [&](int s, int kt) {
        const int k0 = kt * BK;
        const uint32_t abase = sb + s * STAGE_BYTES;
        const uint32_t bbase = abase + A_TILE_BYTES;
        const float* ag = Ag + (size_t)crow * KP + k0;
        const float* bg = Bg + (size_t)crow * KP + k0;
        const float* bg2 = bg + (size_t)128 * KP;
#pragma unroll
        for (int i = 0; i < 4; i++) {
            int q = cq0 + i;
            uint32_t o = (uint32_t)(crow * (PITCH * 4) + q * 16);
            cp_async16(abase + o, ag + q * 4);
            cp_async16(bbase + o, bg + q * 4);
            cp_async16(bbase + o + 128 * (PITCH * 4), bg2 + q * 4);
        }
    };

    float acc[4][8][4];
#pragma unroll
    for (int mf = 0; mf < 4; mf++)
#pragma unroll
        for (int nf = 0; nf < 8; nf++)
#pragma unroll
            for (int r = 0; r < 4; r++) acc[mf][nf][r] = 0.f;

    // prologue: stages 0,1
    load_stage(0, 0); CP_COMMIT();
    load_stage(1, 1); CP_COMMIT();

    int s_cur = 0, s_ld = 2;
    for (int kt = 0; kt < NK; kt++) {
        const int lds = kt + STAGES - 1;
        if (lds < NK) load_stage(s_ld, lds);
        CP_COMMIT();
        CP_WAIT(STAGES - 1);
        __syncthreads();

        const uint32_t* As = (const uint32_t*)(smem + s_cur * STAGE_BYTES);
        const uint32_t* Bs = (const uint32_t*)(smem + s_cur * STAGE_BYTES + A_TILE_BYTES);

#pragma unroll
        for (int kk = 0; kk < 4; kk++) {
            const int kb = kk * 8;
            uint32_t bf[8][2];
#pragma unroll
            for (int nf = 0; nf < 8; nf++) {
                int n = wn * 64 + nf * 8 + g;
                bf[nf][0] = Bs[n * PITCH + kb + tg];
                bf[nf][1] = Bs[n * PITCH + kb + tg + 4];
            }
#pragma unroll
            for (int mf = 0; mf < 4; mf++) {
                int row = wm * 64 + mf * 16 + g;
                uint32_t af[4];
                af[0] = As[row * PITCH + kb + tg];
                af[1] = As[(row + 8) * PITCH + kb + tg];
                af[2] = As[row * PITCH + kb + tg + 4];
                af[3] = As[(row + 8) * PITCH + kb + tg + 4];
#pragma unroll
                for (int nf = 0; nf < 8; nf++)
                    mma_tf32(acc[mf][nf], af, bf[nf]);
            }
        }
        __syncthreads();
        s_cur = (s_cur + 1 == STAGES) ? 0 : s_cur + 1;
        s_ld  = (s_ld  + 1 == STAGES) ? 0 : s_ld  + 1;
    }

    // ---- epilogue: coalesced float2 stores into linear D ----
#pragma unroll
    for (int mf = 0; mf < 4; mf++) {
        int row0 = rowBase + wm * 64 + mf * 16 + g;
#pragma unroll
        for (int nf = 0; nf < 8; nf++) {
            int col = nBase + wn * 64 + nf * 8 + 2 * tg;
            float2 lo = make_float2(acc[mf][nf][0], acc[mf][nf][1]);
            float2 hi = make_float2(acc[mf][nf][2], acc[mf][nf][3]);
            *(float2*)(Dg + (size_t)row0 * NP + col)       = lo;
            *(float2*)(Dg + (size_t)(row0 + 8) * NP + col) = hi;
        }
    }
}

// ---------------------------------------------------------------------------
// combine: out_re = D0 - D1, out_im = D0 + D2, scattered into full grid
// (also writes the guard-column zeros, replacing a separate memset)
// ---------------------------------------------------------------------------
__global__ void combine(const int* __restrict__ sc, float* __restrict__ out) {
    __shared__ int inv[FFT_];
    int tid = threadIdx.x;
    if (tid < FFT_) inv[tid] = -1;
    __syncthreads();
    if (tid < NSC_) inv[sc[tid]] = tid;
    __syncthreads();

    int idx = blockIdx.x * blockDim.x + tid;   // over 2048*14*128
    int c = idx & (FFT_ - 1);
    int t = idx >> 7;
    int sym = t % SYM_;
    int row = t / SYM_;

    float re = 0.f, im = 0.f;
    int j = inv[c];
    if (j >= 0) {
        size_t o = (size_t)row * KP + sym * NSC_ + j;
        float d0 = g_D[0][o], d1 = g_D[1][o], d2 = g_D[2][o];
        re = d0 - d1;
        im = d0 + d2;
    }
    out[idx]         = re;
    out[PLANE + idx] = im;
}

// ---------------------------------------------------------------------------
extern "C" void kernel_launch(void* const* d_in, const int* in_sizes, int n_in,
                              void* d_out, int out_size) {
    const float* xr = (const float*)d_in[0];
    const float* xi = (const float*)d_in[1];
    const float* Cr = (const float*)d_in[2];
    const float* Ci = (const float*)d_in[3];
    const int*   sc = (const int*)d_in[4];
    float* out = (float*)d_out;

    cudaFuncSetAttribute(gemm_mma, cudaFuncAttributeMaxDynamicSharedMemorySize, SMEM_BYTES);

    pack_A<<<dim3(KP / 256, MROWS), 256>>>(xr, xi, sc);
    pack_B<<<dim3(KP / 256, NP), 256>>>(Cr, Ci);

    gemm_mma<<<dim3(3 * NTILES, MROWS / BM), 256, SMEM_BYTES>>>(0);

    combine<<<(MROWS * ROWSTRIDE) / 256, 256>>>(sc, out);
}